// round 16
// baseline (speedup 1.0000x reference)
#include <cuda_runtime.h>
#include <math_constants.h>

#define NS   5
#define NC   64
#define NB   8
#define HIN  512
#define WIN  512
#define HO   257
#define WO   257
#define NPIX (HO*WO)            // 66049
#define NGRP ((NPIX + 3) / 4)   // 16513 groups of 4 pixels

// Piecewise-linear table, k-major, float2 {S1,S2}:
//   P[o](L) = max(S1 + S2*L, 0), k = #{sorted thresholds < L}
__device__ float2 g_tab[NS][65][NC];
__device__ float  g_th [NS][64];
__device__ float  g_wv [NS][4];

// ---------------------------------------------------------------------------
// Precompute (R10-R15 verbatim — measured-best): grid (65, 5) x 64.
// fp64 channel meta + bitonic sort (exact k-bucketing); w2 staged via
// LDG.128; table sums in fp32 with 4 independent split accumulators.
// Implicit PDL completion at kernel end flushes g_* for the main kernel.
// ---------------------------------------------------------------------------
__global__ void __launch_bounds__(64)
precompute_tab(
    const float* __restrict__ lp, const float* __restrict__ hp,
    const float* __restrict__ w1, const float* __restrict__ w2,
    const float* __restrict__ g1, const float* __restrict__ b1,
    const float* __restrict__ m1, const float* __restrict__ v1,
    const float* __restrict__ g2, const float* __restrict__ b2,
    const float* __restrict__ m2, const float* __restrict__ v2)
{
    const int s = blockIdx.y;
    const int k = blockIdx.x;       // 0..64
    const int c = threadIdx.x;      // 0..63

    __shared__ float  sw2[64 * 65];   // padded stride 65: conflict-free columns
    __shared__ float  sAf[64], sBf[64];
    __shared__ float  sthv[64];
    __shared__ int    sidx[64];
    __shared__ int    srk [64];
    __shared__ signed char scls[64];  // 1: A>0, 2: A<0, 3: A==0 && B>0, 0: dead

    // stage w2 with vector loads: 16 LDG.128 per thread
    {
        const float4* w2v = reinterpret_cast<const float4*>(w2) + s * 1024;
        #pragma unroll
        for (int t = 0; t < 16; t++) {
            const int i   = c + t * 64;       // float4 index 0..1023
            const float4 v = w2v[i];
            const int row = i >> 4;           // 16 float4 per row
            const int col = (i & 15) * 4;
            float* dst = &sw2[row * 65 + col];
            dst[0] = v.x; dst[1] = v.y; dst[2] = v.z; dst[3] = v.w;
        }
    }

    // per-channel meta in fp64 (k-bucketing identical to prior rounds)
    {
        double sc1 = (double)g1[s*NC + c] / sqrt((double)v1[s*NC + c] + 1e-5);
        double sh1 = (double)b1[s*NC + c] - (double)m1[s*NC + c] * sc1;
        double A   = (double)w1[s*NC + c] * sc1;
        sAf[c]  = (float)A;
        sBf[c]  = (float)sh1;
        scls[c] = (A > 0.0) ? 1 : (A < 0.0) ? 2 : (sh1 > 0.0) ? 3 : 0;
        sthv[c] = (A != 0.0) ? (float)(-sh1 / A) : CUDART_INF_F;
        sidx[c] = c;
    }
    __syncthreads();

    // bitonic sort of 64 (key sthv, payload sidx)
    for (int ksz = 2; ksz <= 64; ksz <<= 1) {
        for (int j = ksz >> 1; j > 0; j >>= 1) {
            int ixj = c ^ j;
            if (ixj > c) {
                float a = sthv[c], bb = sthv[ixj];
                int   ia = sidx[c], ib = sidx[ixj];
                bool  up = ((c & ksz) == 0);
                if (up ? (a > bb) : (a < bb)) {
                    sthv[c] = bb; sthv[ixj] = a;
                    sidx[c] = ib; sidx[ixj] = ia;
                }
            }
            __syncthreads();
        }
    }

    srk[sidx[c]] = c;
    if (k == 0) {
        g_th[s][c] = sthv[c];
        if (c == 0) {
            g_wv[s][0] = lp[s*2]; g_wv[s][1] = lp[s*2+1];
            g_wv[s][2] = hp[s*2]; g_wv[s][3] = hp[s*2+1];
        }
    }
    __syncthreads();

    // entry (s, k, o = c): fp32 masked sums, 4 independent chains
    const int o = c;
    const double sc2 = (double)g2[s*NC + o] / sqrt((double)v2[s*NC + o] + 1e-5);
    const double sh2 = (double)b2[s*NC + o] - (double)m2[s*NC + o] * sc2;

    float s1a = 0.f, s2a = 0.f, s1b = 0.f, s2b = 0.f;
    float s1c = 0.f, s2c = 0.f, s1d = 0.f, s2d = 0.f;
    #pragma unroll
    for (int cc = 0; cc < 64; cc += 4) {
        #define ACC(CI, S1, S2)                                          \
        {   const int cl = scls[CI];                                     \
            const bool act = (cl == 1) ? (srk[CI] < k)                   \
                           : (cl == 2) ? (srk[CI] >= k)                  \
                                       : (cl == 3);                      \
            if (act) {                                                   \
                const float w = sw2[o*65 + (CI)];                        \
                S1 = fmaf(w, sBf[CI], S1);                               \
                S2 = fmaf(w, sAf[CI], S2);                               \
            }                                                            \
        }
        ACC(cc + 0, s1a, s2a)
        ACC(cc + 1, s1b, s2b)
        ACC(cc + 2, s1c, s2c)
        ACC(cc + 3, s1d, s2d)
        #undef ACC
    }
    const double s1 = (double)((s1a + s1b) + (s1c + s1d));
    const double s2 = (double)((s2a + s2b) + (s2c + s2d));
    g_tab[s][k][o] = make_float2((float)(sc2*s1 + sh2), (float)(sc2*s2));
}

// ---------------------------------------------------------------------------
// Main kernel (R15 verbatim + PDL grid-dependency sync at entry):
// grid (30, 40), thread owns 4 consecutive pixels; streaming STG.128 via
// per-plane shift d = o & 3 with a 7-slot (3 halo + 4 own) shfl window;
// 16-way replicated thresholds for the rank binary search.
// ---------------------------------------------------------------------------
__global__ void __launch_bounds__(256)
dwt_pwl_kernel(const float* __restrict__ x, float* __restrict__ out)
{
    __shared__ float2 stab[65 * 65];     // idx = k*65 + o  (padded stride)
    __shared__ float  sthr[64 * 16];     // thresholds, 16 replicas: [idx*16+rep]

#if __CUDA_ARCH__ >= 900
    // PDL: wait for precompute's implicit completion before reading g_*.
    cudaGridDependencySynchronize();
#endif

    const int sb = blockIdx.y;          // 0..39
    const int s  = sb / NB;
    const int b  = sb - s * NB;

    const float2* gt = &g_tab[s][0][0];
    for (int i = threadIdx.x; i < 65 * 64; i += 256) {
        int k = i >> 6, o = i & 63;
        stab[k * 65 + o] = gt[i];
    }
    for (int i = threadIdx.x; i < 64 * 16; i += 256)
        sthr[i] = g_th[s][i >> 4];
    __syncthreads();

    const float lp0 = g_wv[s][0], lp1 = g_wv[s][1];
    const float hp0 = g_wv[s][2], hp1 = g_wv[s][3];

    const float* __restrict__ xb = x + (size_t)b * HIN * WIN;
    float* __restrict__ outL = out + (size_t)sb * NPIX;
    float* __restrict__ outH = out + (size_t)(NS*NB + sb) * NPIX;
    float* __restrict__ outP = out + (size_t)2*NS*NB*NPIX + (size_t)sb * NC * NPIX;

    const int lane = threadIdx.x & 31;
    const int rep  = lane & 15;          // this lane's threshold replica
    const int gstride = gridDim.x * blockDim.x;

    // rank via binary search in this lane's replica (bank spread: <=2 lanes/bank)
    auto rankOf = [&](float L) -> int {
        const float* th = sthr + rep;
        int kk = (th[31*16]        < L) ? 32 : 0;
        kk += (th[(kk + 15)*16] < L) ? 16 : 0;
        kk += (th[(kk +  7)*16] < L) ?  8 : 0;
        kk += (th[(kk +  3)*16] < L) ?  4 : 0;
        kk += (th[(kk +  1)*16] < L) ?  2 : 0;
        kk += (th[kk*16]        < L) ?  1 : 0;
        return kk;
    };

    // compute L, Hc, rank k for one pixel (fully guarded, incl. bottom row)
    auto pixLHK = [&](int pix, float& L, float& H, int& k) {
        L = 0.f; H = 0.f;
        if (pix >= 0 && pix < NPIX) {
            unsigned up = (unsigned)pix;
            int i = up / WO;
            int j = up - i * WO;
            int r0 = 2*i - 1, r1 = 2*i;
            int c0 = 2*j - 1, c1 = 2*j;
            float x00 = (r0 >= 0  && c0 >= 0 ) ? xb[r0*WIN + c0] : 0.f;
            float x01 = (r0 >= 0  && c1 < WIN) ? xb[r0*WIN + c1] : 0.f;
            float x10 = (r1 < HIN && c0 >= 0 ) ? xb[r1*WIN + c0] : 0.f;
            float x11 = (r1 < HIN && c1 < WIN) ? xb[r1*WIN + c1] : 0.f;
            L = lp0*(lp0*x00 + lp1*x01) + lp1*(lp0*x10 + lp1*x11);
            H = hp0*(hp0*x00 + hp1*x01) + hp1*(hp0*x10 + hp1*x11);
        }
        k = rankOf(L);
    };

    for (int gw = blockIdx.x * 256 + (int)(threadIdx.x & ~31u); gw < NGRP;
         gw += gstride)
    {
        const int g = gw + lane;
        const int pix0 = 4 * g;

        float Ls[7], Hs[7]; int ks[7];
        pixLHK(pix0 + 0, Ls[3], Hs[3], ks[3]);
        pixLHK(pix0 + 1, Ls[4], Hs[4], ks[4]);
        pixLHK(pix0 + 2, Ls[5], Hs[5], ks[5]);
        pixLHK(pix0 + 3, Ls[6], Hs[6], ks[6]);

        // halo (previous group's pixels 1..3) via shfl; lane 0 recomputes
        Ls[0] = __shfl_up_sync(0xffffffffu, Ls[4], 1);
        Ls[1] = __shfl_up_sync(0xffffffffu, Ls[5], 1);
        Ls[2] = __shfl_up_sync(0xffffffffu, Ls[6], 1);
        Hs[0] = __shfl_up_sync(0xffffffffu, Hs[4], 1);
        Hs[1] = __shfl_up_sync(0xffffffffu, Hs[5], 1);
        Hs[2] = __shfl_up_sync(0xffffffffu, Hs[6], 1);
        ks[0] = __shfl_up_sync(0xffffffffu, ks[4], 1);
        ks[1] = __shfl_up_sync(0xffffffffu, ks[5], 1);
        ks[2] = __shfl_up_sync(0xffffffffu, ks[6], 1);
        if (lane == 0) {
            pixLHK(pix0 - 3, Ls[0], Hs[0], ks[0]);
            pixLHK(pix0 - 2, Ls[1], Hs[1], ks[1]);
            pixLHK(pix0 - 1, Ls[2], Hs[2], ks[2]);
        }

        if (g >= NGRP) continue;

        const bool edge = (g == 0) || (g == NGRP - 1);

        if (!edge) {
            // ---- P planes: 16 quads of 4 channels, one streaming STG.128 ----
            float* bp = outP + pix0;
            #pragma unroll
            for (int q = 0; q < 16; q++) {
                const int o0 = 4 * q;
                {   // o0, d=0: slots 3..6, addr +0
                    float2 f0 = stab[ks[3]*65 + o0], f1 = stab[ks[4]*65 + o0];
                    float2 f2 = stab[ks[5]*65 + o0], f3 = stab[ks[6]*65 + o0];
                    float4 v = make_float4(fmaxf(fmaf(f0.y, Ls[3], f0.x), 0.f),
                                           fmaxf(fmaf(f1.y, Ls[4], f1.x), 0.f),
                                           fmaxf(fmaf(f2.y, Ls[5], f2.x), 0.f),
                                           fmaxf(fmaf(f3.y, Ls[6], f3.x), 0.f));
                    __stcs(reinterpret_cast<float4*>(bp), v);
                }
                {   // o0+1, d=1: slots 2..5, addr +NPIX-1
                    float2 f0 = stab[ks[2]*65 + o0+1], f1 = stab[ks[3]*65 + o0+1];
                    float2 f2 = stab[ks[4]*65 + o0+1], f3 = stab[ks[5]*65 + o0+1];
                    float4 v = make_float4(fmaxf(fmaf(f0.y, Ls[2], f0.x), 0.f),
                                           fmaxf(fmaf(f1.y, Ls[3], f1.x), 0.f),
                                           fmaxf(fmaf(f2.y, Ls[4], f2.x), 0.f),
                                           fmaxf(fmaf(f3.y, Ls[5], f3.x), 0.f));
                    __stcs(reinterpret_cast<float4*>(bp + (NPIX - 1)), v);
                }
                {   // o0+2, d=2: slots 1..4, addr +2*NPIX-2
                    float2 f0 = stab[ks[1]*65 + o0+2], f1 = stab[ks[2]*65 + o0+2];
                    float2 f2 = stab[ks[3]*65 + o0+2], f3 = stab[ks[4]*65 + o0+2];
                    float4 v = make_float4(fmaxf(fmaf(f0.y, Ls[1], f0.x), 0.f),
                                           fmaxf(fmaf(f1.y, Ls[2], f1.x), 0.f),
                                           fmaxf(fmaf(f2.y, Ls[3], f2.x), 0.f),
                                           fmaxf(fmaf(f3.y, Ls[4], f3.x), 0.f));
                    __stcs(reinterpret_cast<float4*>(bp + (2*NPIX - 2)), v);
                }
                {   // o0+3, d=3: slots 0..3, addr +3*NPIX-3
                    float2 f0 = stab[ks[0]*65 + o0+3], f1 = stab[ks[1]*65 + o0+3];
                    float2 f2 = stab[ks[2]*65 + o0+3], f3 = stab[ks[3]*65 + o0+3];
                    float4 v = make_float4(fmaxf(fmaf(f0.y, Ls[0], f0.x), 0.f),
                                           fmaxf(fmaf(f1.y, Ls[1], f1.x), 0.f),
                                           fmaxf(fmaf(f2.y, Ls[2], f2.x), 0.f),
                                           fmaxf(fmaf(f3.y, Ls[3], f3.x), 0.f));
                    __stcs(reinterpret_cast<float4*>(bp + (3*NPIX - 3)), v);
                }
                bp += (size_t)4 * NPIX;
            }

            // ---- L / Hc planes: runtime shift (uniform per block) ----
            switch (sb & 3) {
            case 0:
                __stcs(reinterpret_cast<float4*>(outL + pix0),
                       make_float4(Ls[3], Ls[4], Ls[5], Ls[6]));
                __stcs(reinterpret_cast<float4*>(outH + pix0),
                       make_float4(Hs[3], Hs[4], Hs[5], Hs[6]));
                break;
            case 1:
                __stcs(reinterpret_cast<float4*>(outL + pix0 - 1),
                       make_float4(Ls[2], Ls[3], Ls[4], Ls[5]));
                __stcs(reinterpret_cast<float4*>(outH + pix0 - 1),
                       make_float4(Hs[2], Hs[3], Hs[4], Hs[5]));
                break;
            case 2:
                __stcs(reinterpret_cast<float4*>(outL + pix0 - 2),
                       make_float4(Ls[1], Ls[2], Ls[3], Ls[4]));
                __stcs(reinterpret_cast<float4*>(outH + pix0 - 2),
                       make_float4(Hs[1], Hs[2], Hs[3], Hs[4]));
                break;
            default:
                __stcs(reinterpret_cast<float4*>(outL + pix0 - 3),
                       make_float4(Ls[0], Ls[1], Ls[2], Ls[3]));
                __stcs(reinterpret_cast<float4*>(outH + pix0 - 3),
                       make_float4(Hs[0], Hs[1], Hs[2], Hs[3]));
                break;
            }
        } else {
            // ---- edge groups (first/last of plane): masked streaming stores ----
            #pragma unroll 4
            for (int o = 0; o < 64; o++) {
                const int d = o & 3;
                #pragma unroll
                for (int e = 0; e < 4; e++) {
                    int pix = pix0 - d + e;
                    if (pix >= 0 && pix < NPIX) {
                        float2 f = stab[ks[3 - d + e] * 65 + o];
                        __stcs(&outP[(size_t)o * NPIX + pix],
                               fmaxf(fmaf(f.y, Ls[3 - d + e], f.x), 0.f));
                    }
                }
            }
            switch (sb & 3) {
            #define EDGE_LH(D)                                              \
                { _Pragma("unroll")                                         \
                  for (int e = 0; e < 4; e++) {                             \
                      int pix = pix0 - (D) + e;                             \
                      if (pix >= 0 && pix < NPIX) {                         \
                          __stcs(&outL[pix], Ls[3 - (D) + e]);              \
                          __stcs(&outH[pix], Hs[3 - (D) + e]);              \
                      }                                                     \
                  } }
            case 0:  EDGE_LH(0) break;
            case 1:  EDGE_LH(1) break;
            case 2:  EDGE_LH(2) break;
            default: EDGE_LH(3) break;
            #undef EDGE_LH
            }
        }
    }
}

// ---------------------------------------------------------------------------
extern "C" void kernel_launch(void* const* d_in, const int* in_sizes, int n_in,
                              void* d_out, int out_size)
{
    const float* x  = (const float*)d_in[0];
    const float* lp = (const float*)d_in[1];
    const float* hp = (const float*)d_in[2];
    const float* w1 = (const float*)d_in[3];
    const float* w2 = (const float*)d_in[4];
    const float* g1 = (const float*)d_in[5];
    const float* b1 = (const float*)d_in[6];
    const float* m1 = (const float*)d_in[7];
    const float* v1 = (const float*)d_in[8];
    const float* g2 = (const float*)d_in[9];
    const float* b2 = (const float*)d_in[10];
    const float* m2 = (const float*)d_in[11];
    const float* v2 = (const float*)d_in[12];
    float* out = (float*)d_out;

    precompute_tab<<<dim3(65, NS), 64>>>(lp, hp, w1, w2, g1, b1, m1, v1,
                                         g2, b2, m2, v2);

    // Main kernel with programmatic dependent launch: its launch/prologue
    // overlaps precompute execution; cudaGridDependencySynchronize() in the
    // kernel guarantees g_* visibility (implicit completion at precompute end).
    cudaLaunchConfig_t cfg = {};
    cfg.gridDim  = dim3(30, NS * NB);   // 1200 blocks — best-measured config
    cfg.blockDim = dim3(256, 1, 1);
    cfg.dynamicSmemBytes = 0;
    cfg.stream = 0;
    cudaLaunchAttribute attrs[1];
    attrs[0].id = cudaLaunchAttributeProgrammaticStreamSerialization;
    attrs[0].val.programmaticStreamSerializationAllowed = 1;
    cfg.attrs = attrs;
    cfg.numAttrs = 1;
    cudaLaunchKernelEx(&cfg, dwt_pwl_kernel, x, out);
}